// round 7
// baseline (speedup 1.0000x reference)
#include <cuda_runtime.h>
#include <cuda_fp16.h>
#include <cstdint>
#include <math.h>

#define S 1024
#define D 64
#define BH 32
#define KT 1920                    // 1024+512+256+128 concatenated keys
#define OUT_ELEMS (BH * S * D)     // 2,097,152

// ---------- scratch ----------
__device__ __align__(16) __half g_ph[(size_t)BH * S * KT];   // UNNORMALIZED exp(score) fp16
__device__ __align__(16) __half g_qh[BH * S * D];            // query hi
__device__ __align__(16) __half g_ql[BH * S * D];            // query lo
__device__ __align__(16) __half g_projh[BH * KT * D];        // projected pooled keys hi
__device__ __align__(16) __half g_projl[BH * KT * D];        // projected pooled keys lo
__device__ float  g_pv[BH * KT * D];                         // pooled values fp32
__device__ __align__(16) __half g_pvpT[BH * D * KT];         // (A^T A pv)^T fp16
__device__ float  g_psum[(size_t)BH * S * 15];               // per-(row, ntile) exp sums
__device__ float  g_inv[(size_t)BH * S * 4];                 // per-(row, scale) 1/sum
__device__ float  g_mc[896 * 3];                             // tridiag coefs si=1..3

__device__ __forceinline__ void interp_idx(int k, int si, int& i0, int& i1, float& w) {
    int s = 1 << si, Kin = S >> si;
    float src = (k + 0.5f) * (1.0f / (float)s) - 0.5f;
    src = fminf(fmaxf(src, 0.0f), (float)(Kin - 1));
    i0 = (int)src;
    i1 = min(i0 + 1, Kin - 1);
    w = src - (float)i0;
}

__device__ __forceinline__ void mma16816(float* c, const unsigned* a, const unsigned* b) {
    asm volatile(
        "mma.sync.aligned.m16n8k16.row.col.f32.f16.f16.f32 "
        "{%0,%1,%2,%3}, {%4,%5,%6,%7}, {%8,%9}, {%0,%1,%2,%3};\n"
        : "+f"(c[0]), "+f"(c[1]), "+f"(c[2]), "+f"(c[3])
        : "r"(a[0]), "r"(a[1]), "r"(a[2]), "r"(a[3]), "r"(b[0]), "r"(b[1]));
}
__device__ __forceinline__ void ldm_x4(unsigned* r, uint32_t addr) {
    asm volatile("ldmatrix.sync.aligned.m8n8.x4.shared.b16 {%0,%1,%2,%3}, [%4];"
                 : "=r"(r[0]), "=r"(r[1]), "=r"(r[2]), "=r"(r[3]) : "r"(addr));
}
__device__ __forceinline__ uint32_t smem_u32(const void* p) {
    uint32_t a;
    asm("{ .reg .u64 t; cvta.to.shared.u64 t, %1; cvt.u32.u64 %0, t; }" : "=r"(a) : "l"(p));
    return a;
}

// ---------- K0: split-convert query to fp16 hi/lo ----------
__global__ void k_qconv(const float* __restrict__ q) {
    int i = blockIdx.x * 256 + threadIdx.x;
    float x = q[i];
    __half h = __float2half(x);
    g_qh[i] = h;
    g_ql[i] = __float2half(x - __half2float(h));
}

// ---------- K1: avg-pool keys/values + per-scale linear projection ----------
__global__ void k_pool_proj(const float* __restrict__ key,
                            const float* __restrict__ value,
                            const float* __restrict__ W,
                            const float* __restrict__ b) {
    int bh = blockIdx.z;
    int si = blockIdx.y;
    int Ks = S >> si;
    int off = 2048 - (2048 >> si);
    int k0 = blockIdx.x * 16;
    if (k0 >= Ks) return;
    int s = 1 << si;

    __shared__ float sWt[64 * 65];
    __shared__ float sPK[16 * 64];
    int t = threadIdx.x;

    for (int lin = t; lin < 4096; lin += 256) {
        int dout = lin >> 6, din = lin & 63;
        sWt[din * 65 + dout] = W[si * 4096 + lin];
    }

    float invs = 1.0f / (float)s;
#pragma unroll
    for (int j = 0; j < 4; j++) {
        int idx = t + j * 256;
        int r = idx >> 6, e = idx & 63;
        int k = k0 + r;
        const float* kp = key   + ((size_t)bh * S + (size_t)k * s) * D + e;
        const float* vp = value + ((size_t)bh * S + (size_t)k * s) * D + e;
        float ak = 0.f, av = 0.f;
        for (int i = 0; i < s; i++) { ak += kp[i * D]; av += vp[i * D]; }
        ak *= invs; av *= invs;
        sPK[idx] = ak;
        g_pv[((size_t)bh * KT + off + k) * D + e] = av;
    }
    __syncthreads();

    int d  = t & 63;
    int r0 = t >> 6;
    float bias = b[si * 64 + d];
#pragma unroll
    for (int j = 0; j < 4; j++) {
        int r = r0 + j * 4;
        float acc = bias;
        const float* pk = &sPK[r * 64];
#pragma unroll
        for (int e = 0; e < 64; e++) acc += pk[e] * sWt[e * 65 + d];
        size_t oi = ((size_t)bh * KT + off + k0 + r) * D + d;
        __half h = __float2half(acc);
        g_projh[oi] = h;
        g_projl[oi] = __float2half(acc - __half2float(h));
    }
}

// ---------- K2a: tridiagonal coefs of M = A^T A per scale ----------
__global__ void k_mcoef() {
    int idx = blockIdx.x * 256 + threadIdx.x;
    if (idx >= 896) return;
    int si, j;
    if (idx < 512)      { si = 1; j = idx; }
    else if (idx < 768) { si = 2; j = idx - 512; }
    else                { si = 3; j = idx - 768; }
    int s = 1 << si;
    float c0 = 0.f, c1 = 0.f, c2 = 0.f;
    int klo = max(0, s * (j - 1)), khi = min(S, s * (j + 2));
    for (int k = klo; k < khi; k++) {
        int i0, i1; float w;
        interp_idx(k, si, i0, i1, w);
        float aj = (i0 == j ? (1.f - w) : 0.f) + (i1 == j ? w : 0.f);
        if (aj != 0.f) {
            float ajm = (i0 == j - 1 ? (1.f - w) : 0.f) + (i1 == j - 1 ? w : 0.f);
            float ajp = (i0 == j + 1 ? (1.f - w) : 0.f) + (i1 == j + 1 ? w : 0.f);
            c0 += aj * ajm; c1 += aj * aj; c2 += aj * ajp;
        }
    }
    g_mc[idx * 3 + 0] = c0;
    g_mc[idx * 3 + 1] = c1;
    g_mc[idx * 3 + 2] = c2;
}

// ---------- K2b: pvpT = (M pv)^T fp16 ----------
__global__ void k_pvp2() {
    int bh = blockIdx.y;
    int n0 = blockIdx.x * 32;
    int si = (n0 < 1024) ? 0 : (n0 < 1536) ? 1 : (n0 < 1792) ? 2 : 3;
    int off = 2048 - (2048 >> si);
    int j0 = n0 - off;
    int Kin = S >> si;
    int t = threadIdx.x;
    __shared__ float sv[34][64];
    __shared__ __align__(16) __half rt[64][40];
    const float* pvb = g_pv + ((size_t)bh * KT + off) * D;

    for (int i = t; i < 34 * 64; i += 256) {
        int rr = i >> 6, d = i & 63;
        int j = min(max(j0 - 1 + rr, 0), Kin - 1);
        sv[rr][d] = pvb[(size_t)j * D + d];
    }
    __syncthreads();

    if (si == 0) {
        for (int i = t; i < 32 * 64; i += 256) {
            int r = i >> 6, d = i & 63;
            rt[d][r] = __float2half(sv[r + 1][d]);
        }
    } else {
        int mcb = ((si == 1) ? 0 : (si == 2) ? 512 : 768) + j0;
        for (int i = t; i < 32 * 64; i += 256) {
            int r = i >> 6, d = i & 63;
            int j = j0 + r;
            float v = g_mc[(mcb + r) * 3 + 1] * sv[r + 1][d];
            if (j > 0)       v += g_mc[(mcb + r) * 3 + 0] * sv[r][d];
            if (j < Kin - 1) v += g_mc[(mcb + r) * 3 + 2] * sv[r + 2][d];
            rt[d][r] = __float2half(v);
        }
    }
    __syncthreads();
    int d = t >> 2, qv = t & 3;
    *(uint4*)&g_pvpT[((size_t)bh * D + d) * KT + n0 + qv * 8] = *(uint4*)&rt[d][qv * 8];
}

// ---------- K3: fused scores GEMM (ldmatrix + mma.sync) + exp + partial sums ----------
// C tile 128x128, 8 warps (2m x 4n), warp tile 64x32. 3-way fp16 split with
// A-fragment reuse: acc += Ah*Bh + Ah*Bl + Al*Bh.
__global__ __launch_bounds__(256, 1) void k_scores_fused() {
    int bh = blockIdx.z;
    int m0 = blockIdx.y * 128;
    int n0 = blockIdx.x * 128;
    __shared__ __align__(16) __half Ah[128 * 40];
    __shared__ __align__(16) __half Al[128 * 40];
    __shared__ __align__(16) __half Bh[128 * 40];
    __shared__ __align__(16) __half Bl[128 * 40];
    __shared__ float rowsum[128];
    int t = threadIdx.x;
    int warp = t >> 5, lane = t & 31;
    int wm = warp >> 2, wn = warp & 3;
    int lr = lane >> 2, lc = (lane & 3) * 2;

    if (t < 128) rowsum[t] = 0.f;

    uint32_t baseAh = smem_u32(Ah), baseAl = smem_u32(Al);
    uint32_t baseBh = smem_u32(Bh), baseBl = smem_u32(Bl);
    // ldmatrix lane offsets (halves*2 = bytes), stride 40 halves = 80B (conflict-free)
    uint32_t aoff = (uint32_t)(((lane & 15) * 40 + (lane >> 4) * 8) * 2);
    uint32_t boff = (uint32_t)((((lane & 7) + ((lane >> 4) & 1) * 8) * 40 + ((lane >> 3) & 1) * 8) * 2);

    float acc[4][4][4];
#pragma unroll
    for (int i = 0; i < 4; i++)
#pragma unroll
        for (int j = 0; j < 4; j++)
#pragma unroll
            for (int k = 0; k < 4; k++) acc[i][j][k] = 0.f;

    const __half* gah = g_qh    + ((size_t)bh * S + m0) * D;
    const __half* gal = g_ql    + ((size_t)bh * S + m0) * D;
    const __half* gbh = g_projh + ((size_t)bh * KT + n0) * D;
    const __half* gbl = g_projl + ((size_t)bh * KT + n0) * D;

    for (int kc = 0; kc < 64; kc += 32) {
#pragma unroll
        for (int j = 0; j < 2; j++) {
            int i = t + j * 256;
            int r = i >> 2, q4 = i & 3;
            size_t go = (size_t)r * D + kc + q4 * 8;
            int so = r * 40 + q4 * 8;
            *(uint4*)&Ah[so] = *(const uint4*)(gah + go);
            *(uint4*)&Al[so] = *(const uint4*)(gal + go);
            *(uint4*)&Bh[so] = *(const uint4*)(gbh + go);
            *(uint4*)&Bl[so] = *(const uint4*)(gbl + go);
        }
        __syncthreads();

#pragma unroll
        for (int k16 = 0; k16 < 32; k16 += 16) {
            unsigned ah[4][4], al[4][4], bhf[4][2], blf[4][2];
#pragma unroll
            for (int mt = 0; mt < 4; mt++) {
                uint32_t ro = (uint32_t)((wm * 64 + mt * 16) * 80 + k16 * 2);
                ldm_x4(ah[mt], baseAh + ro + aoff);
                ldm_x4(al[mt], baseAl + ro + aoff);
            }
#pragma unroll
            for (int np = 0; np < 2; np++) {
                unsigned r4[4];
                uint32_t ro = (uint32_t)((wn * 32 + np * 16) * 80 + k16 * 2);
                ldm_x4(r4, baseBh + ro + boff);
                bhf[np * 2][0] = r4[0]; bhf[np * 2][1] = r4[1];
                bhf[np * 2 + 1][0] = r4[2]; bhf[np * 2 + 1][1] = r4[3];
                ldm_x4(r4, baseBl + ro + boff);
                blf[np * 2][0] = r4[0]; blf[np * 2][1] = r4[1];
                blf[np * 2 + 1][0] = r4[2]; blf[np * 2 + 1][1] = r4[3];
            }
#pragma unroll
            for (int mt = 0; mt < 4; mt++)
#pragma unroll
                for (int nt = 0; nt < 4; nt++) {
                    mma16816(acc[mt][nt], ah[mt], bhf[nt]);
                    mma16816(acc[mt][nt], ah[mt], blf[nt]);
                    mma16816(acc[mt][nt], al[mt], bhf[nt]);
                }
        }
        __syncthreads();
    }

    // epilogue: e = exp(score), write fp16, accumulate row sums
    __half* C = g_ph + ((size_t)bh * S + m0) * KT + n0;
#pragma unroll
    for (int mt = 0; mt < 4; mt++) {
        float pr = 0.f, pr8 = 0.f;
#pragma unroll
        for (int nt = 0; nt < 4; nt++) {
            int r = wm * 64 + mt * 16 + lr;
            int c = wn * 32 + nt * 8 + lc;
            float e0 = __expf(acc[mt][nt][0] * 0.125f);
            float e1 = __expf(acc[mt][nt][1] * 0.125f);
            float e2 = __expf(acc[mt][nt][2] * 0.125f);
            float e3 = __expf(acc[mt][nt][3] * 0.125f);
            *(__half2*)&C[(size_t)r * KT + c]       = __floats2half2_rn(e0, e1);
            *(__half2*)&C[(size_t)(r + 8) * KT + c] = __floats2half2_rn(e2, e3);
            pr += e0 + e1; pr8 += e2 + e3;
        }
        pr  += __shfl_xor_sync(0xffffffffu, pr, 1);
        pr  += __shfl_xor_sync(0xffffffffu, pr, 2);
        pr8 += __shfl_xor_sync(0xffffffffu, pr8, 1);
        pr8 += __shfl_xor_sync(0xffffffffu, pr8, 2);
        if ((lane & 3) == 0) {
            atomicAdd(&rowsum[wm * 64 + mt * 16 + lr], pr);
            atomicAdd(&rowsum[wm * 64 + mt * 16 + lr + 8], pr8);
        }
    }
    __syncthreads();
    if (t < 128)
        g_psum[((size_t)bh * S + m0 + t) * 15 + blockIdx.x] = rowsum[t];
}

// ---------- K4: inv_sum per (bh,row,scale) ----------
__global__ void k_rsum() {
    int idx = blockIdx.x * 256 + threadIdx.x;
    const float* p = g_psum + (size_t)idx * 15;
    float s0 = 0.f, s1 = 0.f, s2 = 0.f;
#pragma unroll
    for (int i = 0; i < 8; i++)  s0 += p[i];
#pragma unroll
    for (int i = 8; i < 12; i++) s1 += p[i];
    s2 = p[12] + p[13];
    float* o = g_inv + (size_t)idx * 4;
    o[0] = 1.0f / s0; o[1] = 1.0f / s1; o[2] = 1.0f / s2; o[3] = 1.0f / p[14];
}

// ---------- K5: out = 0.25 * probs @ pvp (ldmatrix mma), norm on load ----------
// C tile 128x64, 8 warps (4m x 2n), K chunk 64 (stride 72 halves = 144B, conflict-free).
__global__ __launch_bounds__(256, 1) void k_out_mma(float* __restrict__ out) {
    int bh = blockIdx.y;
    int m0 = blockIdx.x * 128;
    __shared__ __align__(16) __half Ps[128 * 72];
    __shared__ __align__(16) __half Vs[64 * 72];
    int t = threadIdx.x;
    int warp = t >> 5, lane = t & 31;
    int wm = warp >> 1, wn = warp & 1;
    int lr = lane >> 2, lc = (lane & 3) * 2;

    uint32_t baseP = smem_u32(Ps), baseV = smem_u32(Vs);
    uint32_t aoff = (uint32_t)(((lane & 15) * 72 + (lane >> 4) * 8) * 2);
    uint32_t boff = (uint32_t)((((lane & 7) + ((lane >> 4) & 1) * 8) * 72 + ((lane >> 3) & 1) * 8) * 2);

    float acc[2][4][4];
#pragma unroll
    for (int i = 0; i < 2; i++)
#pragma unroll
        for (int j = 0; j < 4; j++)
#pragma unroll
            for (int k = 0; k < 4; k++) acc[i][j][k] = 0.f;

    const __half* P = g_ph   + ((size_t)bh * S + m0) * KT;
    const __half* V = g_pvpT + (size_t)bh * D * KT;
    const float* IV = g_inv + ((size_t)bh * S + m0) * 4;

    for (int kc = 0; kc < KT; kc += 64) {
        int ks = (kc < 1024) ? 0 : (kc < 1536) ? 1 : (kc < 1792) ? 2 : 3;
#pragma unroll
        for (int j = 0; j < 4; j++) {
            int i = t + j * 256;                // 0..1023
            int r = i >> 3, q8 = i & 7;
            __half2 iv2 = __float2half2_rn(IV[r * 4 + ks]);
            uint4 u = *(const uint4*)(P + (size_t)r * KT + kc + q8 * 8);
            __half2* hp = (__half2*)&u;
#pragma unroll
            for (int x = 0; x < 4; x++) hp[x] = __hmul2(hp[x], iv2);
            *(uint4*)&Ps[r * 72 + q8 * 8] = u;
        }
#pragma unroll
        for (int j = 0; j < 2; j++) {
            int i = t + j * 256;                // 0..511
            int r = i >> 3, q8 = i & 7;
            *(uint4*)&Vs[r * 72 + q8 * 8] =
                *(const uint4*)(V + (size_t)r * KT + kc + q8 * 8);
        }
        __syncthreads();

#pragma unroll
        for (int k16 = 0; k16 < 64; k16 += 16) {
            unsigned af[2][4], bf[4][2];
#pragma unroll
            for (int mt = 0; mt < 2; mt++) {
                uint32_t ro = (uint32_t)((wm * 32 + mt * 16) * 144 + k16 * 2);
                ldm_x4(af[mt], baseP + ro + aoff);
            }
#pragma unroll
            for (int np = 0; np < 2; np++) {
                unsigned r4[4];
                uint32_t ro = (uint32_t)((wn * 32 + np * 16) * 144 + k16 * 2);
                ldm_x4(r4, baseV + ro + boff);
                bf[np * 2][0] = r4[0]; bf[np * 2][1] = r4[1];
                bf[np * 2 + 1][0] = r4[2]; bf[np * 2 + 1][1] = r4[3];
            }
#pragma unroll
            for (int mt = 0; mt < 2; mt++)
#pragma unroll
                for (int nt = 0; nt < 4; nt++)
                    mma16816(acc[mt][nt], af[mt], bf[nt]);
        }
        __syncthreads();
    }

    float* Co = out + (size_t)bh * S * D + (size_t)m0 * D;
#pragma unroll
    for (int mt = 0; mt < 2; mt++) {
#pragma unroll
        for (int nt = 0; nt < 4; nt++) {
            int r = wm * 32 + mt * 16 + lr;
            int c = wn * 32 + nt * 8 + lc;
            Co[(size_t)r * D + c]           = acc[mt][nt][0] * 0.25f;
            Co[(size_t)r * D + c + 1]       = acc[mt][nt][1] * 0.25f;
            Co[(size_t)(r + 8) * D + c]     = acc[mt][nt][2] * 0.25f;
            Co[(size_t)(r + 8) * D + c + 1] = acc[mt][nt][3] * 0.25f;
        }
    }
}

// ---------- K6: combined_attention, one block per (bh,q), smem row + float4 stores ----------
__global__ __launch_bounds__(256) void k_attn(float* __restrict__ out) {
    int bh = blockIdx.y, q = blockIdx.x;
    __shared__ __align__(16) __half row[KT];
    __shared__ float inv4s[4];
    int t = threadIdx.x;
    const __half* grow = g_ph + ((size_t)bh * S + q) * KT;
    if (t < 240) *(uint4*)&row[t * 8] = *(const uint4*)&grow[t * 8];
    if (t < 4) inv4s[t] = g_inv[((size_t)bh * S + q) * 4 + t];
    __syncthreads();

    int k0 = t * 4;
    float r4[4];
#pragma unroll
    for (int j = 0; j < 4; j++) {
        int k = k0 + j;
        float acc = __half2float(row[k]) * inv4s[0];
#pragma unroll
        for (int si = 1; si < 4; si++) {
            int off = 2048 - (2048 >> si);
            int i0, i1; float w;
            interp_idx(k, si, i0, i1, w);
            acc += (__half2float(row[off + i0]) * (1.0f - w) +
                    __half2float(row[off + i1]) * w) * inv4s[si];
        }
        r4[j] = acc * 0.25f;
    }
    *(float4*)(out + (size_t)OUT_ELEMS + ((size_t)bh * S + q) * S + k0) = *(float4*)r4;
}

// ---------- launch ----------
extern "C" void kernel_launch(void* const* d_in, const int* in_sizes, int n_in,
                              void* d_out, int out_size) {
    const float* q = (const float*)d_in[0];
    const float* k = (const float*)d_in[1];
    const float* v = (const float*)d_in[2];
    const float* W = (const float*)d_in[3];
    const float* b = (const float*)d_in[4];
    float* out = (float*)d_out;

    k_qconv       <<<8192, 256>>>(q);
    k_pool_proj   <<<dim3(64, 4, 32), 256>>>(k, v, W, b);
    k_mcoef       <<<4, 256>>>();
    k_pvp2        <<<dim3(60, 32), 256>>>();
    k_scores_fused<<<dim3(15, 8, 32), 256>>>();
    k_rsum        <<<128, 256>>>();
    k_out_mma     <<<dim3(8, 32), 256>>>(out);
    if (out_size >= (int)(OUT_ELEMS + (size_t)BH * S * S))
        k_attn<<<dim3(1024, 32), 256>>>(out);
}

// round 9
// speedup vs baseline: 1.4296x; 1.4296x over previous
#include <cuda_runtime.h>
#include <cuda_fp16.h>
#include <cstdint>
#include <math.h>

#define S 1024
#define D 64
#define BH 32
#define KT 1920                    // 1024+512+256+128 concatenated keys
#define OUT_ELEMS (BH * S * D)     // 2,097,152

// ---------- scratch ----------
__device__ __align__(16) __half g_ph[(size_t)BH * S * KT];  // UNNORMALIZED exp(score) fp16
__device__ __align__(16) __half g_projh[BH * KT * D];       // projected pooled keys (hi)
__device__ __align__(16) __half g_projl[BH * KT * D];       // projected pooled keys (lo)
__device__ __align__(16) __half g_qh[BH * S * D];           // query hi
__device__ __align__(16) __half g_ql[BH * S * D];           // query lo
__device__ float  g_pv[BH * KT * D];                        // pooled values fp32
__device__ __align__(16) __half g_pvpT[BH * D * KT];        // (A^T A pv)^T [bh][d][kt] fp16
__device__ float  g_psum[(size_t)BH * S * 15];              // per-(row, ntile) exp sums
__device__ float  g_inv[(size_t)BH * S * 4];                // per-(row, scale) 1/sum
__device__ float  g_mc[896 * 3];                            // tridiag coefs for si=1..3

__device__ __forceinline__ void interp_idx(int k, int si, int& i0, int& i1, float& w) {
    int s = 1 << si, Kin = S >> si;
    float src = (k + 0.5f) * (1.0f / (float)s) - 0.5f;
    src = fminf(fmaxf(src, 0.0f), (float)(Kin - 1));
    i0 = (int)src;
    i1 = min(i0 + 1, Kin - 1);
    w = src - (float)i0;
}

__device__ __forceinline__ void mma16816(float* c, const unsigned* a, const unsigned* b) {
    asm volatile(
        "mma.sync.aligned.m16n8k16.row.col.f32.f16.f16.f32 "
        "{%0,%1,%2,%3}, {%4,%5,%6,%7}, {%8,%9}, {%0,%1,%2,%3};\n"
        : "+f"(c[0]), "+f"(c[1]), "+f"(c[2]), "+f"(c[3])
        : "r"(a[0]), "r"(a[1]), "r"(a[2]), "r"(a[3]), "r"(b[0]), "r"(b[1]));
}

// ---------- K0: split-convert query to fp16 hi/lo ----------
__global__ void k_qconv(const float* __restrict__ q) {
    int i = blockIdx.x * 256 + threadIdx.x;
    float x = q[i];
    __half h = __float2half(x);
    g_qh[i] = h;
    g_ql[i] = __float2half(x - __half2float(h));
}

// ---------- K1: avg-pool keys/values + per-scale linear projection ----------
__global__ void k_pool_proj(const float* __restrict__ key,
                            const float* __restrict__ value,
                            const float* __restrict__ W,
                            const float* __restrict__ b) {
    int bh = blockIdx.z;
    int si = blockIdx.y;
    int Ks = S >> si;
    int off = 2048 - (2048 >> si);
    int k0 = blockIdx.x * 16;
    if (k0 >= Ks) return;
    int s = 1 << si;

    __shared__ float sWt[64 * 65];
    __shared__ float sPK[16 * 64];
    int t = threadIdx.x;

    for (int lin = t; lin < 4096; lin += 256) {
        int dout = lin >> 6, din = lin & 63;
        sWt[din * 65 + dout] = W[si * 4096 + lin];
    }

    float invs = 1.0f / (float)s;
#pragma unroll
    for (int j = 0; j < 4; j++) {
        int idx = t + j * 256;
        int r = idx >> 6, e = idx & 63;
        int k = k0 + r;
        const float* kp = key   + ((size_t)bh * S + (size_t)k * s) * D + e;
        const float* vp = value + ((size_t)bh * S + (size_t)k * s) * D + e;
        float ak = 0.f, av = 0.f;
        for (int i = 0; i < s; i++) { ak += kp[i * D]; av += vp[i * D]; }
        ak *= invs; av *= invs;
        sPK[idx] = ak;
        g_pv[((size_t)bh * KT + off + k) * D + e] = av;
    }
    __syncthreads();

    int d  = t & 63;
    int r0 = t >> 6;
    float bias = b[si * 64 + d];
#pragma unroll
    for (int j = 0; j < 4; j++) {
        int r = r0 + j * 4;
        float acc = bias;
        const float* pk = &sPK[r * 64];
#pragma unroll
        for (int e = 0; e < 64; e++) acc += pk[e] * sWt[e * 65 + d];
        size_t oi = ((size_t)bh * KT + off + k0 + r) * D + d;
        __half h = __float2half(acc);
        g_projh[oi] = h;
        g_projl[oi] = __float2half(acc - __half2float(h));
    }
}

// ---------- K2a: tridiagonal coefs of M = A^T A per scale ----------
__global__ void k_mcoef() {
    int idx = blockIdx.x * 256 + threadIdx.x;
    if (idx >= 896) return;
    int si, j;
    if (idx < 512)      { si = 1; j = idx; }
    else if (idx < 768) { si = 2; j = idx - 512; }
    else                { si = 3; j = idx - 768; }
    int s = 1 << si;
    float c0 = 0.f, c1 = 0.f, c2 = 0.f;
    int klo = max(0, s * (j - 1)), khi = min(S, s * (j + 2));
    for (int k = klo; k < khi; k++) {
        int i0, i1; float w;
        interp_idx(k, si, i0, i1, w);
        float aj = (i0 == j ? (1.f - w) : 0.f) + (i1 == j ? w : 0.f);
        if (aj != 0.f) {
            float ajm = (i0 == j - 1 ? (1.f - w) : 0.f) + (i1 == j - 1 ? w : 0.f);
            float ajp = (i0 == j + 1 ? (1.f - w) : 0.f) + (i1 == j + 1 ? w : 0.f);
            c0 += aj * ajm; c1 += aj * aj; c2 += aj * ajp;
        }
    }
    g_mc[idx * 3 + 0] = c0;
    g_mc[idx * 3 + 1] = c1;
    g_mc[idx * 3 + 2] = c2;
}

// ---------- K2b: pvpT = (M pv)^T fp16, tridiagonal apply + smem transpose ----------
__global__ void k_pvp2() {
    int bh = blockIdx.y;
    int n0 = blockIdx.x * 32;
    int si = (n0 < 1024) ? 0 : (n0 < 1536) ? 1 : (n0 < 1792) ? 2 : 3;
    int off = 2048 - (2048 >> si);
    int j0 = n0 - off;
    int Kin = S >> si;
    int t = threadIdx.x;
    __shared__ float sv[34][64];
    __shared__ __align__(16) __half rt[64][40];
    const float* pvb = g_pv + ((size_t)bh * KT + off) * D;

    for (int i = t; i < 34 * 64; i += 256) {
        int rr = i >> 6, d = i & 63;
        int j = min(max(j0 - 1 + rr, 0), Kin - 1);
        sv[rr][d] = pvb[(size_t)j * D + d];
    }
    __syncthreads();

    if (si == 0) {
        for (int i = t; i < 32 * 64; i += 256) {
            int r = i >> 6, d = i & 63;
            rt[d][r] = __float2half(sv[r + 1][d]);
        }
    } else {
        int mcb = ((si == 1) ? 0 : (si == 2) ? 512 : 768) + j0;
        for (int i = t; i < 32 * 64; i += 256) {
            int r = i >> 6, d = i & 63;
            int j = j0 + r;
            float v = g_mc[(mcb + r) * 3 + 1] * sv[r + 1][d];
            if (j > 0)       v += g_mc[(mcb + r) * 3 + 0] * sv[r][d];
            if (j < Kin - 1) v += g_mc[(mcb + r) * 3 + 2] * sv[r + 2][d];
            rt[d][r] = __float2half(v);
        }
    }
    __syncthreads();
    int d = t >> 2, qv = t & 3;
    *(uint4*)&g_pvpT[((size_t)bh * D + d) * KT + n0 + qv * 8] = *(uint4*)&rt[d][qv * 8];
}

// ---------- K3: fused scores GEMM + exp + partial row sums (round-3 proven) ----------
__global__ __launch_bounds__(256) void k_scores_fused() {
    int bh = blockIdx.z;
    int m0 = blockIdx.y * 128;
    int n0 = blockIdx.x * 128;
    __shared__ __align__(16) __half Ah[128 * 40];
    __shared__ __align__(16) __half Al[128 * 40];
    __shared__ __align__(16) __half Bh[128 * 40];
    __shared__ __align__(16) __half Bl[128 * 40];
    __shared__ float rowsum[128];
    int t = threadIdx.x;
    int warp = t >> 5, lane = t & 31;
    int wm = warp >> 2, wn = warp & 3;
    int lr = lane >> 2, lc = (lane & 3) * 2;

    if (t < 128) rowsum[t] = 0.f;

    float acc[4][4][4];
#pragma unroll
    for (int i = 0; i < 4; i++)
#pragma unroll
        for (int j = 0; j < 4; j++)
#pragma unroll
            for (int k = 0; k < 4; k++) acc[i][j][k] = 0.f;

    const __half* gah = g_qh    + ((size_t)bh * S + m0) * D;
    const __half* gal = g_ql    + ((size_t)bh * S + m0) * D;
    const __half* gbh = g_projh + ((size_t)bh * KT + n0) * D;
    const __half* gbl = g_projl + ((size_t)bh * KT + n0) * D;

    for (int kc = 0; kc < 64; kc += 32) {
#pragma unroll
        for (int j = 0; j < 2; j++) {
            int i = t + j * 256;
            int r = i >> 2, q4 = i & 3;
            size_t go = (size_t)r * D + kc + q4 * 8;
            int so = r * 40 + q4 * 8;
            *(uint4*)&Ah[so] = *(const uint4*)(gah + go);
            *(uint4*)&Al[so] = *(const uint4*)(gal + go);
            *(uint4*)&Bh[so] = *(const uint4*)(gbh + go);
            *(uint4*)&Bl[so] = *(const uint4*)(gbl + go);
        }
        __syncthreads();

#pragma unroll
        for (int sp = 0; sp < 3; sp++) {
            const __half* As_ = (sp == 2) ? Al : Ah;
            const __half* Bs_ = (sp == 1) ? Bl : Bh;
#pragma unroll
            for (int k16 = 0; k16 < 32; k16 += 16) {
                unsigned afr[4][4];
#pragma unroll
                for (int mt = 0; mt < 4; mt++) {
                    int r = wm * 64 + mt * 16 + lr;
                    int c = k16 + lc;
                    afr[mt][0] = *(const unsigned*)&As_[r * 40 + c];
                    afr[mt][1] = *(const unsigned*)&As_[(r + 8) * 40 + c];
                    afr[mt][2] = *(const unsigned*)&As_[r * 40 + c + 8];
                    afr[mt][3] = *(const unsigned*)&As_[(r + 8) * 40 + c + 8];
                }
                unsigned bfr[4][2];
#pragma unroll
                for (int nt = 0; nt < 4; nt++) {
                    int n = wn * 32 + nt * 8 + lr;
                    bfr[nt][0] = *(const unsigned*)&Bs_[n * 40 + k16 + lc];
                    bfr[nt][1] = *(const unsigned*)&Bs_[n * 40 + k16 + lc + 8];
                }
#pragma unroll
                for (int mt = 0; mt < 4; mt++)
#pragma unroll
                    for (int nt = 0; nt < 4; nt++)
                        mma16816(acc[mt][nt], afr[mt], bfr[nt]);
            }
        }
        __syncthreads();
    }

    // epilogue: e = exp(score), write fp16, accumulate row sums
    __half* C = g_ph + ((size_t)bh * S + m0) * KT + n0;
#pragma unroll
    for (int mt = 0; mt < 4; mt++) {
        float pr = 0.f, pr8 = 0.f;
#pragma unroll
        for (int nt = 0; nt < 4; nt++) {
            int r = wm * 64 + mt * 16 + lr;
            int c = wn * 32 + nt * 8 + lc;
            float e0 = __expf(acc[mt][nt][0] * 0.125f);
            float e1 = __expf(acc[mt][nt][1] * 0.125f);
            float e2 = __expf(acc[mt][nt][2] * 0.125f);
            float e3 = __expf(acc[mt][nt][3] * 0.125f);
            *(__half2*)&C[(size_t)r * KT + c]       = __floats2half2_rn(e0, e1);
            *(__half2*)&C[(size_t)(r + 8) * KT + c] = __floats2half2_rn(e2, e3);
            pr += e0 + e1; pr8 += e2 + e3;
        }
        pr  += __shfl_xor_sync(0xffffffffu, pr, 1);
        pr  += __shfl_xor_sync(0xffffffffu, pr, 2);
        pr8 += __shfl_xor_sync(0xffffffffu, pr8, 1);
        pr8 += __shfl_xor_sync(0xffffffffu, pr8, 2);
        if ((lane & 3) == 0) {
            atomicAdd(&rowsum[wm * 64 + mt * 16 + lr], pr);
            atomicAdd(&rowsum[wm * 64 + mt * 16 + lr + 8], pr8);
        }
    }
    __syncthreads();
    if (t < 128)
        g_psum[((size_t)bh * S + m0 + t) * 15 + blockIdx.x] = rowsum[t];
}

// ---------- K4: inv_sum per (bh,row,scale) ----------
__global__ void k_rsum() {
    int idx = blockIdx.x * 256 + threadIdx.x;
    const float* p = g_psum + (size_t)idx * 15;
    float s0 = 0.f, s1 = 0.f, s2 = 0.f;
#pragma unroll
    for (int i = 0; i < 8; i++)  s0 += p[i];
#pragma unroll
    for (int i = 8; i < 12; i++) s1 += p[i];
    s2 = p[12] + p[13];
    float* o = g_inv + (size_t)idx * 4;
    o[0] = 1.0f / s0; o[1] = 1.0f / s1; o[2] = 1.0f / s2; o[3] = 1.0f / p[14];
}

// ---------- K5: out = 0.25 * probs @ pvp, normalization applied on load ----------
__global__ __launch_bounds__(256) void k_out_mma(float* __restrict__ out) {
    int bh = blockIdx.y;
    int m0 = blockIdx.x * 128;
    __shared__ __align__(16) __half Ps[128 * 40];
    __shared__ __align__(16) __half Vs[64 * 40];
    int t = threadIdx.x;
    int warp = t >> 5, lane = t & 31;
    int wm = warp >> 1, wn = warp & 1;
    int lr = lane >> 2, lc = (lane & 3) * 2;

    float acc[2][4][4];
#pragma unroll
    for (int i = 0; i < 2; i++)
#pragma unroll
        for (int j = 0; j < 4; j++)
#pragma unroll
            for (int k = 0; k < 4; k++) acc[i][j][k] = 0.f;

    const __half* P = g_ph   + ((size_t)bh * S + m0) * KT;
    const __half* V = g_pvpT + (size_t)bh * D * KT;
    const float* IV = g_inv + ((size_t)bh * S + m0) * 4;

    for (int kc = 0; kc < KT; kc += 32) {
        int ks = (kc < 1024) ? 0 : (kc < 1536) ? 1 : (kc < 1792) ? 2 : 3;
#pragma unroll
        for (int j = 0; j < 2; j++) {
            int i = t + j * 256;
            int r = i >> 2, q4 = i & 3;
            __half2 iv2 = __float2half2_rn(IV[r * 4 + ks]);
            uint4 u = *(const uint4*)(P + (size_t)r * KT + kc + q4 * 8);
            __half2* hp = (__half2*)&u;
#pragma unroll
            for (int x = 0; x < 4; x++) hp[x] = __hmul2(hp[x], iv2);
            *(uint4*)&Ps[r * 40 + q4 * 8] = u;
        }
        if (t < 256) {
            int r = t >> 2, q4 = t & 3;
            *(uint4*)&Vs[r * 40 + q4 * 8] =
                *(const uint4*)(V + (size_t)r * KT + kc + q4 * 8);
        }
        __syncthreads();

#pragma unroll
        for (int k16 = 0; k16 < 32; k16 += 16) {
            unsigned afr[2][4];
#pragma unroll
            for (int mt = 0; mt < 2; mt++) {
                int r = wm * 32 + mt * 16 + lr;
                int c = k16 + lc;
                afr[mt][0] = *(const unsigned*)&Ps[r * 40 + c];
                afr[mt][1] = *(const unsigned*)&Ps[(r + 8) * 40 + c];
                afr[mt][2] = *(const unsigned*)&Ps[r * 40 + c + 8];
                afr[mt][3] = *(const unsigned*)&Ps[(r + 8) * 40 + c + 8];
            }
            unsigned bfr[4][2];
#pragma unroll
            for (int nt = 0; nt < 4; nt++) {
                int n = wn * 32 + nt * 8 + lr;
                bfr[nt][0] = *(const unsigned*)&Vs[n * 40 + k16 + lc];
                bfr[nt][1] = *(const unsigned*)&Vs[n * 40 + k16 + lc + 8];
            }
#pragma unroll
            for (int mt = 0; mt < 2; mt++)
#pragma unroll
                for (int nt = 0; nt < 4; nt++)
                    mma16816(acc[mt][nt], afr[mt], bfr[nt]);
        }
        __syncthreads();
    }

    float* Co = out + (size_t)bh * S * D + (size_t)m0 * D;
#pragma unroll
    for (int mt = 0; mt < 2; mt++) {
#pragma unroll
        for (int nt = 0; nt < 4; nt++) {
            int r = wm * 32 + mt * 16 + lr;
            int c = wn * 32 + nt * 8 + lc;
            Co[(size_t)r * D + c]           = acc[mt][nt][0] * 0.25f;
            Co[(size_t)r * D + c + 1]       = acc[mt][nt][1] * 0.25f;
            Co[(size_t)(r + 8) * D + c]     = acc[mt][nt][2] * 0.25f;
            Co[(size_t)(r + 8) * D + c + 1] = acc[mt][nt][3] * 0.25f;
        }
    }
}

// ---------- K6: combined_attention, one block per (bh,q), smem row + float4 stores ----------
__global__ __launch_bounds__(256) void k_attn(float* __restrict__ out) {
    int bh = blockIdx.y, q = blockIdx.x;
    __shared__ __align__(16) __half row[KT];
    __shared__ float inv4s[4];
    int t = threadIdx.x;
    const __half* grow = g_ph + ((size_t)bh * S + q) * KT;
    if (t < 240) *(uint4*)&row[t * 8] = *(const uint4*)&grow[t * 8];
    if (t < 4) inv4s[t] = g_inv[((size_t)bh * S + q) * 4 + t];
    __syncthreads();

    int k0 = t * 4;
    float r4[4];
#pragma unroll
    for (int j = 0; j < 4; j++) {
        int k = k0 + j;
        float acc = __half2float(row[k]) * inv4s[0];
#pragma unroll
        for (int si = 1; si < 4; si++) {
            int off = 2048 - (2048 >> si);
            int i0, i1; float w;
            interp_idx(k, si, i0, i1, w);
            acc += (__half2float(row[off + i0]) * (1.0f - w) +
                    __half2float(row[off + i1]) * w) * inv4s[si];
        }
        r4[j] = acc * 0.25f;
    }
    *(float4*)(out + (size_t)OUT_ELEMS + ((size_t)bh * S + q) * S + k0) = *(float4*)r4;
}

// ---------- launch ----------
extern "C" void kernel_launch(void* const* d_in, const int* in_sizes, int n_in,
                              void* d_out, int out_size) {
    const float* q = (const float*)d_in[0];
    const float* k = (const float*)d_in[1];
    const float* v = (const float*)d_in[2];
    const float* W = (const float*)d_in[3];
    const float* b = (const float*)d_in[4];
    float* out = (float*)d_out;

    k_qconv       <<<8192, 256>>>(q);
    k_pool_proj   <<<dim3(64, 4, 32), 256>>>(k, v, W, b);
    k_mcoef       <<<4, 256>>>();
    k_pvp2        <<<dim3(60, 32), 256>>>();
    k_scores_fused<<<dim3(15, 8, 32), 256>>>();
    k_rsum        <<<128, 256>>>();
    k_out_mma     <<<dim3(8, 32), 256>>>(out);
    if (out_size >= (int)(OUT_ELEMS + (size_t)BH * S * S))
        k_attn<<<dim3(1024, 32), 256>>>(out);
}

// round 11
// speedup vs baseline: 1.5156x; 1.0602x over previous
#include <cuda_runtime.h>
#include <cuda_fp16.h>
#include <cstdint>
#include <math.h>

#define S 1024
#define D 64
#define BH 32
#define KT 1920                    // 1024+512+256+128 concatenated keys
#define OUT_ELEMS (BH * S * D)     // 2,097,152

// ---------- scratch ----------
__device__ __align__(16) __half g_ph[(size_t)BH * S * KT];  // UNNORMALIZED exp(score) fp16
__device__ __align__(16) __half g_projh[BH * KT * D];       // projected pooled keys (hi)
__device__ __align__(16) __half g_projl[BH * KT * D];       // projected pooled keys (lo)
__device__ __align__(16) __half g_qh[BH * S * D];           // query hi
__device__ float  g_pv[BH * KT * D];                        // pooled values fp32
__device__ __align__(16) __half g_pvpT[BH * D * KT];        // (A^T A pv)^T [bh][d][kt] fp16
__device__ float  g_psum[(size_t)BH * S * 15];              // per-(row, ntile) exp sums
__device__ float  g_inv[(size_t)BH * S * 4];                // per-(row, scale) 1/sum
__device__ float  g_mc[896 * 3];                            // tridiag coefs for si=1..3

__device__ __forceinline__ void interp_idx(int k, int si, int& i0, int& i1, float& w) {
    int s = 1 << si, Kin = S >> si;
    float src = (k + 0.5f) * (1.0f / (float)s) - 0.5f;
    src = fminf(fmaxf(src, 0.0f), (float)(Kin - 1));
    i0 = (int)src;
    i1 = min(i0 + 1, Kin - 1);
    w = src - (float)i0;
}

__device__ __forceinline__ void mma16816(float* c, const unsigned* a, const unsigned* b) {
    asm volatile(
        "mma.sync.aligned.m16n8k16.row.col.f32.f16.f16.f32 "
        "{%0,%1,%2,%3}, {%4,%5,%6,%7}, {%8,%9}, {%0,%1,%2,%3};\n"
        : "+f"(c[0]), "+f"(c[1]), "+f"(c[2]), "+f"(c[3])
        : "r"(a[0]), "r"(a[1]), "r"(a[2]), "r"(a[3]), "r"(b[0]), "r"(b[1]));
}

// ---------- K0: query -> fp16 (hi only; ql correction term dropped, see notes) ----------
__global__ void k_qconv(const float* __restrict__ q) {
    int i = blockIdx.x * 256 + threadIdx.x;
    g_qh[i] = __float2half(q[i]);
}

// ---------- K1: avg-pool keys/values + per-scale linear projection ----------
__global__ void k_pool_proj(const float* __restrict__ key,
                            const float* __restrict__ value,
                            const float* __restrict__ W,
                            const float* __restrict__ b) {
    int bh = blockIdx.z;
    int si = blockIdx.y;
    int Ks = S >> si;
    int off = 2048 - (2048 >> si);
    int k0 = blockIdx.x * 16;
    if (k0 >= Ks) return;
    int s = 1 << si;

    __shared__ float sWt[64 * 65];
    __shared__ float sPK[16 * 64];
    int t = threadIdx.x;

    for (int lin = t; lin < 4096; lin += 256) {
        int dout = lin >> 6, din = lin & 63;
        sWt[din * 65 + dout] = W[si * 4096 + lin];
    }

    float invs = 1.0f / (float)s;
#pragma unroll
    for (int j = 0; j < 4; j++) {
        int idx = t + j * 256;
        int r = idx >> 6, e = idx & 63;
        int k = k0 + r;
        const float* kp = key   + ((size_t)bh * S + (size_t)k * s) * D + e;
        const float* vp = value + ((size_t)bh * S + (size_t)k * s) * D + e;
        float ak = 0.f, av = 0.f;
        for (int i = 0; i < s; i++) { ak += kp[i * D]; av += vp[i * D]; }
        ak *= invs; av *= invs;
        sPK[idx] = ak;
        g_pv[((size_t)bh * KT + off + k) * D + e] = av;
    }
    __syncthreads();

    int d  = t & 63;
    int r0 = t >> 6;
    float bias = b[si * 64 + d];
#pragma unroll
    for (int j = 0; j < 4; j++) {
        int r = r0 + j * 4;
        float acc = bias;
        const float* pk = &sPK[r * 64];
#pragma unroll
        for (int e = 0; e < 64; e++) acc += pk[e] * sWt[e * 65 + d];
        size_t oi = ((size_t)bh * KT + off + k0 + r) * D + d;
        __half h = __float2half(acc);
        g_projh[oi] = h;
        g_projl[oi] = __float2half(acc - __half2float(h));
    }
}

// ---------- K2a: tridiagonal coefs of M = A^T A per scale ----------
__global__ void k_mcoef() {
    int idx = blockIdx.x * 256 + threadIdx.x;
    if (idx >= 896) return;
    int si, j;
    if (idx < 512)      { si = 1; j = idx; }
    else if (idx < 768) { si = 2; j = idx - 512; }
    else                { si = 3; j = idx - 768; }
    int s = 1 << si;
    float c0 = 0.f, c1 = 0.f, c2 = 0.f;
    int klo = max(0, s * (j - 1)), khi = min(S, s * (j + 2));
    for (int k = klo; k < khi; k++) {
        int i0, i1; float w;
        interp_idx(k, si, i0, i1, w);
        float aj = (i0 == j ? (1.f - w) : 0.f) + (i1 == j ? w : 0.f);
        if (aj != 0.f) {
            float ajm = (i0 == j - 1 ? (1.f - w) : 0.f) + (i1 == j - 1 ? w : 0.f);
            float ajp = (i0 == j + 1 ? (1.f - w) : 0.f) + (i1 == j + 1 ? w : 0.f);
            c0 += aj * ajm; c1 += aj * aj; c2 += aj * ajp;
        }
    }
    g_mc[idx * 3 + 0] = c0;
    g_mc[idx * 3 + 1] = c1;
    g_mc[idx * 3 + 2] = c2;
}

// ---------- K2b: pvpT = (M pv)^T fp16, tridiagonal apply + smem transpose ----------
__global__ void k_pvp2() {
    int bh = blockIdx.y;
    int n0 = blockIdx.x * 32;
    int si = (n0 < 1024) ? 0 : (n0 < 1536) ? 1 : (n0 < 1792) ? 2 : 3;
    int off = 2048 - (2048 >> si);
    int j0 = n0 - off;
    int Kin = S >> si;
    int t = threadIdx.x;
    __shared__ float sv[34][64];
    __shared__ __align__(16) __half rt[64][40];
    const float* pvb = g_pv + ((size_t)bh * KT + off) * D;

    for (int i = t; i < 34 * 64; i += 256) {
        int rr = i >> 6, d = i & 63;
        int j = min(max(j0 - 1 + rr, 0), Kin - 1);
        sv[rr][d] = pvb[(size_t)j * D + d];
    }
    __syncthreads();

    if (si == 0) {
        for (int i = t; i < 32 * 64; i += 256) {
            int r = i >> 6, d = i & 63;
            rt[d][r] = __float2half(sv[r + 1][d]);
        }
    } else {
        int mcb = ((si == 1) ? 0 : (si == 2) ? 512 : 768) + j0;
        for (int i = t; i < 32 * 64; i += 256) {
            int r = i >> 6, d = i & 63;
            int j = j0 + r;
            float v = g_mc[(mcb + r) * 3 + 1] * sv[r + 1][d];
            if (j > 0)       v += g_mc[(mcb + r) * 3 + 0] * sv[r][d];
            if (j < Kin - 1) v += g_mc[(mcb + r) * 3 + 2] * sv[r + 2][d];
            rt[d][r] = __float2half(v);
        }
    }
    __syncthreads();
    int d = t >> 2, qv = t & 3;
    *(uint4*)&g_pvpT[((size_t)bh * D + d) * KT + n0 + qv * 8] = *(uint4*)&rt[d][qv * 8];
}

// ---------- K3: fused scores GEMM + exp + partial row sums ----------
// 2-term split: scores = qh*projh + qh*projl (= qh*proj; ql term dropped, err ~1.2e-4).
// A fragments loaded once per k16, shared across both B terms.
__global__ __launch_bounds__(256) void k_scores_fused() {
    int bh = blockIdx.z;
    int m0 = blockIdx.y * 128;
    int n0 = blockIdx.x * 128;
    __shared__ __align__(16) __half Ah[128 * 40];
    __shared__ __align__(16) __half Bh[128 * 40];
    __shared__ __align__(16) __half Bl[128 * 40];
    __shared__ float rowsum[128];
    int t = threadIdx.x;
    int warp = t >> 5, lane = t & 31;
    int wm = warp >> 2, wn = warp & 3;
    int lr = lane >> 2, lc = (lane & 3) * 2;

    if (t < 128) rowsum[t] = 0.f;

    float acc[4][4][4];
#pragma unroll
    for (int i = 0; i < 4; i++)
#pragma unroll
        for (int j = 0; j < 4; j++)
#pragma unroll
            for (int k = 0; k < 4; k++) acc[i][j][k] = 0.f;

    const __half* gah = g_qh    + ((size_t)bh * S + m0) * D;
    const __half* gbh = g_projh + ((size_t)bh * KT + n0) * D;
    const __half* gbl = g_projl + ((size_t)bh * KT + n0) * D;

    for (int kc = 0; kc < 64; kc += 32) {
#pragma unroll
        for (int j = 0; j < 2; j++) {
            int i = t + j * 256;
            int r = i >> 2, q4 = i & 3;
            size_t go = (size_t)r * D + kc + q4 * 8;
            int so = r * 40 + q4 * 8;
            *(uint4*)&Ah[so] = *(const uint4*)(gah + go);
            *(uint4*)&Bh[so] = *(const uint4*)(gbh + go);
            *(uint4*)&Bl[so] = *(const uint4*)(gbl + go);
        }
        __syncthreads();

#pragma unroll
        for (int k16 = 0; k16 < 32; k16 += 16) {
            unsigned afr[4][4];
#pragma unroll
            for (int mt = 0; mt < 4; mt++) {
                int r = wm * 64 + mt * 16 + lr;
                int c = k16 + lc;
                afr[mt][0] = *(const unsigned*)&Ah[r * 40 + c];
                afr[mt][1] = *(const unsigned*)&Ah[(r + 8) * 40 + c];
                afr[mt][2] = *(const unsigned*)&Ah[r * 40 + c + 8];
                afr[mt][3] = *(const unsigned*)&Ah[(r + 8) * 40 + c + 8];
            }
            unsigned bh_[4][2], bl_[4][2];
#pragma unroll
            for (int nt = 0; nt < 4; nt++) {
                int n = wn * 32 + nt * 8 + lr;
                bh_[nt][0] = *(const unsigned*)&Bh[n * 40 + k16 + lc];
                bh_[nt][1] = *(const unsigned*)&Bh[n * 40 + k16 + lc + 8];
                bl_[nt][0] = *(const unsigned*)&Bl[n * 40 + k16 + lc];
                bl_[nt][1] = *(const unsigned*)&Bl[n * 40 + k16 + lc + 8];
            }
#pragma unroll
            for (int mt = 0; mt < 4; mt++)
#pragma unroll
                for (int nt = 0; nt < 4; nt++) {
                    mma16816(acc[mt][nt], afr[mt], bh_[nt]);
                    mma16816(acc[mt][nt], afr[mt], bl_[nt]);
                }
        }
        __syncthreads();
    }

    // epilogue: e = exp(score), write fp16, accumulate row sums
    __half* C = g_ph + ((size_t)bh * S + m0) * KT + n0;
#pragma unroll
    for (int mt = 0; mt < 4; mt++) {
        float pr = 0.f, pr8 = 0.f;
#pragma unroll
        for (int nt = 0; nt < 4; nt++) {
            int r = wm * 64 + mt * 16 + lr;
            int c = wn * 32 + nt * 8 + lc;
            float e0 = __expf(acc[mt][nt][0] * 0.125f);
            float e1 = __expf(acc[mt][nt][1] * 0.125f);
            float e2 = __expf(acc[mt][nt][2] * 0.125f);
            float e3 = __expf(acc[mt][nt][3] * 0.125f);
            *(__half2*)&C[(size_t)r * KT + c]       = __floats2half2_rn(e0, e1);
            *(__half2*)&C[(size_t)(r + 8) * KT + c] = __floats2half2_rn(e2, e3);
            pr += e0 + e1; pr8 += e2 + e3;
        }
        pr  += __shfl_xor_sync(0xffffffffu, pr, 1);
        pr  += __shfl_xor_sync(0xffffffffu, pr, 2);
        pr8 += __shfl_xor_sync(0xffffffffu, pr8, 1);
        pr8 += __shfl_xor_sync(0xffffffffu, pr8, 2);
        if ((lane & 3) == 0) {
            atomicAdd(&rowsum[wm * 64 + mt * 16 + lr], pr);
            atomicAdd(&rowsum[wm * 64 + mt * 16 + lr + 8], pr8);
        }
    }
    __syncthreads();
    if (t < 128)
        g_psum[((size_t)bh * S + m0 + t) * 15 + blockIdx.x] = rowsum[t];
}

// ---------- K4: inv_sum per (bh,row,scale) ----------
__global__ void k_rsum() {
    int idx = blockIdx.x * 256 + threadIdx.x;
    const float* p = g_psum + (size_t)idx * 15;
    float s0 = 0.f, s1 = 0.f, s2 = 0.f;
#pragma unroll
    for (int i = 0; i < 8; i++)  s0 += p[i];
#pragma unroll
    for (int i = 8; i < 12; i++) s1 += p[i];
    s2 = p[12] + p[13];
    float* o = g_inv + (size_t)idx * 4;
    o[0] = 1.0f / s0; o[1] = 1.0f / s1; o[2] = 1.0f / s2; o[3] = 1.0f / p[14];
}

// ---------- K5: out = 0.25 * probs @ pvp, 64x64 tiles, 128 threads ----------
__global__ __launch_bounds__(128) void k_out_mma(float* __restrict__ out) {
    int bh = blockIdx.y;
    int m0 = blockIdx.x * 64;
    __shared__ __align__(16) __half Ps[64 * 40];
    __shared__ __align__(16) __half Vs[64 * 40];
    int t = threadIdx.x;
    int warp = t >> 5, lane = t & 31;
    int wm = warp >> 1, wn = warp & 1;       // 2 x 2 warps, 32x32 warp tiles
    int lr = lane >> 2, lc = (lane & 3) * 2;

    float acc[2][4][4];
#pragma unroll
    for (int i = 0; i < 2; i++)
#pragma unroll
        for (int j = 0; j < 4; j++)
#pragma unroll
            for (int k = 0; k < 4; k++) acc[i][j][k] = 0.f;

    const __half* P = g_ph   + ((size_t)bh * S + m0) * KT;
    const __half* V = g_pvpT + (size_t)bh * D * KT;
    const float* IV = g_inv + ((size_t)bh * S + m0) * 4;

    for (int kc = 0; kc < KT; kc += 32) {
        int ks = (kc < 1024) ? 0 : (kc < 1536) ? 1 : (kc < 1792) ? 2 : 3;
#pragma unroll
        for (int j = 0; j < 2; j++) {
            int i = t + j * 128;            // 0..255 uint4 slots (64 rows x 4)
            int r = i >> 2, q4 = i & 3;
            __half2 iv2 = __float2half2_rn(IV[r * 4 + ks]);
            uint4 u = *(const uint4*)(P + (size_t)r * KT + kc + q4 * 8);
            __half2* hp = (__half2*)&u;
#pragma unroll
            for (int x = 0; x < 4; x++) hp[x] = __hmul2(hp[x], iv2);
            *(uint4*)&Ps[r * 40 + q4 * 8] = u;
        }
#pragma unroll
        for (int j = 0; j < 2; j++) {
            int i = t + j * 128;
            int r = i >> 2, q4 = i & 3;
            *(uint4*)&Vs[r * 40 + q4 * 8] =
                *(const uint4*)(V + (size_t)r * KT + kc + q4 * 8);
        }
        __syncthreads();

#pragma unroll
        for (int k16 = 0; k16 < 32; k16 += 16) {
            unsigned afr[2][4];
#pragma unroll
            for (int mt = 0; mt < 2; mt++) {
                int r = wm * 32 + mt * 16 + lr;
                int c = k16 + lc;
                afr[mt][0] = *(const unsigned*)&Ps[r * 40 + c];
                afr[mt][1] = *(const unsigned*)&Ps[(r + 8) * 40 + c];
                afr[mt][2] = *(const unsigned*)&Ps[r * 40 + c + 8];
                afr[mt][3] = *(const unsigned*)&Ps[(r + 8) * 40 + c + 8];
            }
            unsigned bfr[4][2];
#pragma unroll
            for (int nt = 0; nt < 4; nt++) {
                int n = wn * 32 + nt * 8 + lr;
                bfr[nt][0] = *(const unsigned*)&Vs[n * 40 + k16 + lc];
                bfr[nt][1] = *(const unsigned*)&Vs[n * 40 + k16 + lc + 8];
            }
#pragma unroll
            for (int mt = 0; mt < 2; mt++)
#pragma unroll
                for (int nt = 0; nt < 4; nt++)
                    mma16816(acc[mt][nt], afr[mt], bfr[nt]);
        }
        __syncthreads();
    }

    float* Co = out + (size_t)bh * S * D + (size_t)m0 * D;
#pragma unroll
    for (int mt = 0; mt < 2; mt++) {
#pragma unroll
        for (int nt = 0; nt < 4; nt++) {
            int r = wm * 32 + mt * 16 + lr;
            int c = wn * 32 + nt * 8 + lc;
            Co[(size_t)r * D + c]           = acc[mt][nt][0] * 0.25f;
            Co[(size_t)r * D + c + 1]       = acc[mt][nt][1] * 0.25f;
            Co[(size_t)(r + 8) * D + c]     = acc[mt][nt][2] * 0.25f;
            Co[(size_t)(r + 8) * D + c + 1] = acc[mt][nt][3] * 0.25f;
        }
    }
}

// ---------- K6: combined_attention, one block per (bh,q), smem row + float4 stores ----------
__global__ __launch_bounds__(256) void k_attn(float* __restrict__ out) {
    int bh = blockIdx.y, q = blockIdx.x;
    __shared__ __align__(16) __half row[KT];
    __shared__ float inv4s[4];
    int t = threadIdx.x;
    const __half* grow = g_ph + ((size_t)bh * S + q) * KT;
    if (t < 240) *(uint4*)&row[t * 8] = *(const uint4*)&grow[t * 8];
    if (t < 4) inv4s[t] = g_inv[((size_t)bh * S + q) * 4 + t];
    __syncthreads();

    int k0 = t * 4;
    float r4[4];
#pragma unroll
    for (int j = 0; j < 4; j++) {
        int k = k0 + j;
        float acc = __half2float(row[k]) * inv4s[0];
#pragma unroll
        for (int si = 1; si < 4; si++) {
            int off = 2048 - (2048 >> si);
            int i0, i1; float w;
            interp_idx(k, si, i0, i1, w);
            acc += (__half2float(row[off + i0]) * (1.0f - w) +
                    __half2float(row[off + i1]) * w) * inv4s[si];
        }
        r4[j] = acc * 0.25f;
    }
    *(float4*)(out + (size_t)OUT_ELEMS + ((size_t)bh * S + q) * S + k0) = *(float4*)r4;
}

// ---------- launch ----------
extern "C" void kernel_launch(void* const* d_in, const int* in_sizes, int n_in,
                              void* d_out, int out_size) {
    const float* q = (const float*)d_in[0];
    const float* k = (const float*)d_in[1];
    const float* v = (const float*)d_in[2];
    const float* W = (const float*)d_in[3];
    const float* b = (const float*)d_in[4];
    float* out = (float*)d_out;

    k_qconv       <<<8192, 256>>>(q);
    k_pool_proj   <<<dim3(64, 4, 32), 256>>>(k, v, W, b);
    k_mcoef       <<<4, 256>>>();
    k_pvp2        <<<dim3(60, 32), 256>>>();
    k_scores_fused<<<dim3(15, 8, 32), 256>>>();
    k_rsum        <<<128, 256>>>();
    k_out_mma     <<<dim3(16, 32), 128>>>(out);
    if (out_size >= (int)(OUT_ELEMS + (size_t)BH * S * S))
        k_attn<<<dim3(1024, 32), 256>>>(out);
}

// round 13
// speedup vs baseline: 1.6066x; 1.0600x over previous
#include <cuda_runtime.h>
#include <cuda_fp16.h>
#include <cstdint>
#include <math.h>

#define S 1024
#define D 64
#define BH 32
#define KT 1920                    // 1024+512+256+128 concatenated keys
#define OUT_ELEMS (BH * S * D)     // 2,097,152

// ---------- scratch ----------
__device__ __align__(16) __half g_ph[(size_t)BH * S * KT];  // UNNORMALIZED exp(score) fp16
__device__ __align__(16) __half g_proj[BH * KT * D];        // projected pooled keys fp16
__device__ __align__(16) __half g_qh[BH * S * D];           // query fp16
__device__ float  g_pv[BH * KT * D];                        // pooled values fp32
__device__ __align__(16) __half g_pvpT[BH * D * KT];        // (A^T A pv)^T [bh][d][kt] fp16
__device__ float  g_psum[(size_t)BH * S * 15];              // per-(row, ntile) exp sums
__device__ float  g_inv[(size_t)BH * S * 4];                // per-(row, scale) 1/sum
__device__ float  g_mc[896 * 3];                            // tridiag coefs for si=1..3

__device__ __forceinline__ void interp_idx(int k, int si, int& i0, int& i1, float& w) {
    int s = 1 << si, Kin = S >> si;
    float src = (k + 0.5f) * (1.0f / (float)s) - 0.5f;
    src = fminf(fmaxf(src, 0.0f), (float)(Kin - 1));
    i0 = (int)src;
    i1 = min(i0 + 1, Kin - 1);
    w = src - (float)i0;
}

__device__ __forceinline__ void mma16816(float* c, const unsigned* a, const unsigned* b) {
    asm volatile(
        "mma.sync.aligned.m16n8k16.row.col.f32.f16.f16.f32 "
        "{%0,%1,%2,%3}, {%4,%5,%6,%7}, {%8,%9}, {%0,%1,%2,%3};\n"
        : "+f"(c[0]), "+f"(c[1]), "+f"(c[2]), "+f"(c[3])
        : "r"(a[0]), "r"(a[1]), "r"(a[2]), "r"(a[3]), "r"(b[0]), "r"(b[1]));
}

// ---------- K0: query -> fp16 ----------
__global__ void k_qconv(const float* __restrict__ q) {
    int i = blockIdx.x * 256 + threadIdx.x;
    g_qh[i] = __float2half(q[i]);
}

// ---------- K1: avg-pool keys/values + per-scale linear projection ----------
__global__ void k_pool_proj(const float* __restrict__ key,
                            const float* __restrict__ value,
                            const float* __restrict__ W,
                            const float* __restrict__ b) {
    int bh = blockIdx.z;
    int si = blockIdx.y;
    int Ks = S >> si;
    int off = 2048 - (2048 >> si);
    int k0 = blockIdx.x * 16;
    if (k0 >= Ks) return;
    int s = 1 << si;

    __shared__ float sWt[64 * 65];
    __shared__ float sPK[16 * 64];
    int t = threadIdx.x;

    for (int lin = t; lin < 4096; lin += 256) {
        int dout = lin >> 6, din = lin & 63;
        sWt[din * 65 + dout] = W[si * 4096 + lin];
    }

    float invs = 1.0f / (float)s;
#pragma unroll
    for (int j = 0; j < 4; j++) {
        int idx = t + j * 256;
        int r = idx >> 6, e = idx & 63;
        int k = k0 + r;
        const float* kp = key   + ((size_t)bh * S + (size_t)k * s) * D + e;
        const float* vp = value + ((size_t)bh * S + (size_t)k * s) * D + e;
        float ak = 0.f, av = 0.f;
        for (int i = 0; i < s; i++) { ak += kp[i * D]; av += vp[i * D]; }
        ak *= invs; av *= invs;
        sPK[idx] = ak;
        g_pv[((size_t)bh * KT + off + k) * D + e] = av;
    }
    __syncthreads();

    int d  = t & 63;
    int r0 = t >> 6;
    float bias = b[si * 64 + d];
#pragma unroll
    for (int j = 0; j < 4; j++) {
        int r = r0 + j * 4;
        float acc = bias;
        const float* pk = &sPK[r * 64];
#pragma unroll
        for (int e = 0; e < 64; e++) acc += pk[e] * sWt[e * 65 + d];
        g_proj[((size_t)bh * KT + off + k0 + r) * D + d] = __float2half(acc);
    }
}

// ---------- K2a: tridiagonal coefs of M = A^T A per scale ----------
__global__ void k_mcoef() {
    int idx = blockIdx.x * 256 + threadIdx.x;
    if (idx >= 896) return;
    int si, j;
    if (idx < 512)      { si = 1; j = idx; }
    else if (idx < 768) { si = 2; j = idx - 512; }
    else                { si = 3; j = idx - 768; }
    int s = 1 << si;
    float c0 = 0.f, c1 = 0.f, c2 = 0.f;
    int klo = max(0, s * (j - 1)), khi = min(S, s * (j + 2));
    for (int k = klo; k < khi; k++) {
        int i0, i1; float w;
        interp_idx(k, si, i0, i1, w);
        float aj = (i0 == j ? (1.f - w) : 0.f) + (i1 == j ? w : 0.f);
        if (aj != 0.f) {
            float ajm = (i0 == j - 1 ? (1.f - w) : 0.f) + (i1 == j - 1 ? w : 0.f);
            float ajp = (i0 == j + 1 ? (1.f - w) : 0.f) + (i1 == j + 1 ? w : 0.f);
            c0 += aj * ajm; c1 += aj * aj; c2 += aj * ajp;
        }
    }
    g_mc[idx * 3 + 0] = c0;
    g_mc[idx * 3 + 1] = c1;
    g_mc[idx * 3 + 2] = c2;
}

// ---------- K2b: pvpT = (M pv)^T fp16, tridiagonal apply + smem transpose ----------
__global__ void k_pvp2() {
    int bh = blockIdx.y;
    int n0 = blockIdx.x * 32;
    int si = (n0 < 1024) ? 0 : (n0 < 1536) ? 1 : (n0 < 1792) ? 2 : 3;
    int off = 2048 - (2048 >> si);
    int j0 = n0 - off;
    int Kin = S >> si;
    int t = threadIdx.x;
    __shared__ float sv[34][64];
    __shared__ __align__(16) __half rt[64][40];
    const float* pvb = g_pv + ((size_t)bh * KT + off) * D;

    for (int i = t; i < 34 * 64; i += 256) {
        int rr = i >> 6, d = i & 63;
        int j = min(max(j0 - 1 + rr, 0), Kin - 1);
        sv[rr][d] = pvb[(size_t)j * D + d];
    }
    __syncthreads();

    if (si == 0) {
        for (int i = t; i < 32 * 64; i += 256) {
            int r = i >> 6, d = i & 63;
            rt[d][r] = __float2half(sv[r + 1][d]);
        }
    } else {
        int mcb = ((si == 1) ? 0 : (si == 2) ? 512 : 768) + j0;
        for (int i = t; i < 32 * 64; i += 256) {
            int r = i >> 6, d = i & 63;
            int j = j0 + r;
            float v = g_mc[(mcb + r) * 3 + 1] * sv[r + 1][d];
            if (j > 0)       v += g_mc[(mcb + r) * 3 + 0] * sv[r][d];
            if (j < Kin - 1) v += g_mc[(mcb + r) * 3 + 2] * sv[r + 2][d];
            rt[d][r] = __float2half(v);
        }
    }
    __syncthreads();
    int d = t >> 2, qv = t & 3;
    *(uint4*)&g_pvpT[((size_t)bh * D + d) * KT + n0 + qv * 8] = *(uint4*)&rt[d][qv * 8];
}

// ---------- K3: fused scores GEMM + exp + partial row sums ----------
// Single-term fp16: scores = qh*proj (proj rounded once; score err ~3e-4).
__global__ __launch_bounds__(256) void k_scores_fused() {
    int bh = blockIdx.z;
    int m0 = blockIdx.y * 128;
    int n0 = blockIdx.x * 128;
    __shared__ __align__(16) __half Ah[128 * 40];
    __shared__ __align__(16) __half Bh[128 * 40];
    __shared__ float rowsum[128];
    int t = threadIdx.x;
    int warp = t >> 5, lane = t & 31;
    int wm = warp >> 2, wn = warp & 3;
    int lr = lane >> 2, lc = (lane & 3) * 2;

    if (t < 128) rowsum[t] = 0.f;

    float acc[4][4][4];
#pragma unroll
    for (int i = 0; i < 4; i++)
#pragma unroll
        for (int j = 0; j < 4; j++)
#pragma unroll
            for (int k = 0; k < 4; k++) acc[i][j][k] = 0.f;

    const __half* gah = g_qh   + ((size_t)bh * S + m0) * D;
    const __half* gbh = g_proj + ((size_t)bh * KT + n0) * D;

    for (int kc = 0; kc < 64; kc += 32) {
#pragma unroll
        for (int j = 0; j < 2; j++) {
            int i = t + j * 256;
            int r = i >> 2, q4 = i & 3;
            size_t go = (size_t)r * D + kc + q4 * 8;
            int so = r * 40 + q4 * 8;
            *(uint4*)&Ah[so] = *(const uint4*)(gah + go);
            *(uint4*)&Bh[so] = *(const uint4*)(gbh + go);
        }
        __syncthreads();

#pragma unroll
        for (int k16 = 0; k16 < 32; k16 += 16) {
            unsigned afr[4][4];
#pragma unroll
            for (int mt = 0; mt < 4; mt++) {
                int r = wm * 64 + mt * 16 + lr;
                int c = k16 + lc;
                afr[mt][0] = *(const unsigned*)&Ah[r * 40 + c];
                afr[mt][1] = *(const unsigned*)&Ah[(r + 8) * 40 + c];
                afr[mt][2] = *(const unsigned*)&Ah[r * 40 + c + 8];
                afr[mt][3] = *(const unsigned*)&Ah[(r + 8) * 40 + c + 8];
            }
            unsigned bfr[4][2];
#pragma unroll
            for (int nt = 0; nt < 4; nt++) {
                int n = wn * 32 + nt * 8 + lr;
                bfr[nt][0] = *(const unsigned*)&Bh[n * 40 + k16 + lc];
                bfr[nt][1] = *(const unsigned*)&Bh[n * 40 + k16 + lc + 8];
            }
#pragma unroll
            for (int mt = 0; mt < 4; mt++)
#pragma unroll
                for (int nt = 0; nt < 4; nt++)
                    mma16816(acc[mt][nt], afr[mt], bfr[nt]);
        }
        __syncthreads();
    }

    // epilogue: e = exp(score), write fp16, accumulate row sums
    __half* C = g_ph + ((size_t)bh * S + m0) * KT + n0;
#pragma unroll
    for (int mt = 0; mt < 4; mt++) {
        float pr = 0.f, pr8 = 0.f;
#pragma unroll
        for (int nt = 0; nt < 4; nt++) {
            int r = wm * 64 + mt * 16 + lr;
            int c = wn * 32 + nt * 8 + lc;
            float e0 = __expf(acc[mt][nt][0] * 0.125f);
            float e1 = __expf(acc[mt][nt][1] * 0.125f);
            float e2 = __expf(acc[mt][nt][2] * 0.125f);
            float e3 = __expf(acc[mt][nt][3] * 0.125f);
            *(__half2*)&C[(size_t)r * KT + c]       = __floats2half2_rn(e0, e1);
            *(__half2*)&C[(size_t)(r + 8) * KT + c] = __floats2half2_rn(e2, e3);
            pr += e0 + e1; pr8 += e2 + e3;
        }
        pr  += __shfl_xor_sync(0xffffffffu, pr, 1);
        pr  += __shfl_xor_sync(0xffffffffu, pr, 2);
        pr8 += __shfl_xor_sync(0xffffffffu, pr8, 1);
        pr8 += __shfl_xor_sync(0xffffffffu, pr8, 2);
        if ((lane & 3) == 0) {
            atomicAdd(&rowsum[wm * 64 + mt * 16 + lr], pr);
            atomicAdd(&rowsum[wm * 64 + mt * 16 + lr + 8], pr8);
        }
    }
    __syncthreads();
    if (t < 128)
        g_psum[((size_t)bh * S + m0 + t) * 15 + blockIdx.x] = rowsum[t];
}

// ---------- K4: inv_sum per (bh,row,scale) ----------
__global__ void k_rsum() {
    int idx = blockIdx.x * 256 + threadIdx.x;
    const float* p = g_psum + (size_t)idx * 15;
    float s0 = 0.f, s1 = 0.f, s2 = 0.f;
#pragma unroll
    for (int i = 0; i < 8; i++)  s0 += p[i];
#pragma unroll
    for (int i = 8; i < 12; i++) s1 += p[i];
    s2 = p[12] + p[13];
    float* o = g_inv + (size_t)idx * 4;
    o[0] = 1.0f / s0; o[1] = 1.0f / s1; o[2] = 1.0f / s2; o[3] = 1.0f / p[14];
}

// ---------- K5: out = 0.25 * probs @ pvp, 64x64 tiles, 128 threads ----------
__global__ __launch_bounds__(128) void k_out_mma(float* __restrict__ out) {
    int bh = blockIdx.y;
    int m0 = blockIdx.x * 64;
    __shared__ __align__(16) __half Ps[64 * 40];
    __shared__ __align__(16) __half Vs[64 * 40];
    int t = threadIdx.x;
    int warp = t >> 5, lane = t & 31;
    int wm = warp >> 1, wn = warp & 1;       // 2 x 2 warps, 32x32 warp tiles
    int lr = lane >> 2, lc = (lane & 3) * 2;

    float acc[2][4][4];
#pragma unroll
    for (int i = 0; i < 2; i++)
#pragma unroll
        for (int j = 0; j < 4; j++)
#pragma unroll
            for (int k = 0; k < 4; k++) acc[i][j][k] = 0.f;

    const __half* P = g_ph   + ((size_t)bh * S + m0) * KT;
    const __half* V = g_pvpT + (size_t)bh * D * KT;
    const float* IV = g_inv + ((size_t)bh * S + m0) * 4;

    for (int kc = 0; kc < KT; kc += 32) {
        int ks = (kc < 1024) ? 0 : (kc < 1536) ? 1 : (kc < 1792) ? 2 : 3;
#pragma unroll
        for (int j = 0; j < 2; j++) {
            int i = t + j * 128;            // 0..255 uint4 slots (64 rows x 4)
            int r = i >> 2, q4 = i & 3;
            __half2 iv2 = __float2half2_rn(IV[r * 4 + ks]);
            uint4 u = *(const uint4*)(P + (size_t)r * KT + kc + q4 * 8);
            __half2* hp = (__half2*)&u;
#pragma unroll
            for (int x = 0; x < 4; x++) hp[x] = __hmul2(hp[x], iv2);
            *(uint4*)&Ps[r * 40 + q4 * 8] = u;
        }
#pragma unroll
        for (int j = 0; j < 2; j++) {
            int i = t + j * 128;
            int r = i >> 2, q4 = i & 3;
            *(uint4*)&Vs[r * 40 + q4 * 8] =
                *(const uint4*)(V + (size_t)r * KT + kc + q4 * 8);
        }
        __syncthreads();

#pragma unroll
        for (int k16 = 0; k16 < 32; k16 += 16) {
            unsigned afr[2][4];
#pragma unroll
            for (int mt = 0; mt < 2; mt++) {
                int r = wm * 32 + mt * 16 + lr;
                int c = k16 + lc;
                afr[mt][0] = *(const unsigned*)&Ps[r * 40 + c];
                afr[mt][1] = *(const unsigned*)&Ps[(r + 8) * 40 + c];
                afr[mt][2] = *(const unsigned*)&Ps[r * 40 + c + 8];
                afr[mt][3] = *(const unsigned*)&Ps[(r + 8) * 40 + c + 8];
            }
            unsigned bfr[4][2];
#pragma unroll
            for (int nt = 0; nt < 4; nt++) {
                int n = wn * 32 + nt * 8 + lr;
                bfr[nt][0] = *(const unsigned*)&Vs[n * 40 + k16 + lc];
                bfr[nt][1] = *(const unsigned*)&Vs[n * 40 + k16 + lc + 8];
            }
#pragma unroll
            for (int mt = 0; mt < 2; mt++)
#pragma unroll
                for (int nt = 0; nt < 4; nt++)
                    mma16816(acc[mt][nt], afr[mt], bfr[nt]);
        }
        __syncthreads();
    }

    float* Co = out + (size_t)bh * S * D + (size_t)m0 * D;
#pragma unroll
    for (int mt = 0; mt < 2; mt++) {
#pragma unroll
        for (int nt = 0; nt < 4; nt++) {
            int r = wm * 32 + mt * 16 + lr;
            int c = wn * 32 + nt * 8 + lc;
            Co[(size_t)r * D + c]           = acc[mt][nt][0] * 0.25f;
            Co[(size_t)r * D + c + 1]       = acc[mt][nt][1] * 0.25f;
            Co[(size_t)(r + 8) * D + c]     = acc[mt][nt][2] * 0.25f;
            Co[(size_t)(r + 8) * D + c + 1] = acc[mt][nt][3] * 0.25f;
        }
    }
}

// ---------- K6: combined_attention, one block per (bh,q), smem row + float4 stores ----------
__global__ __launch_bounds__(256) void k_attn(float* __restrict__ out) {
    int bh = blockIdx.y, q = blockIdx.x;
    __shared__ __align__(16) __half row[KT];
    __shared__ float inv4s[4];
    int t = threadIdx.x;
    const __half* grow = g_ph + ((size_t)bh * S + q) * KT;
    if (t < 240) *(uint4*)&row[t * 8] = *(const uint4*)&grow[t * 8];
    if (t < 4) inv4s[t] = g_inv[((size_t)bh * S + q) * 4 + t];
    __syncthreads();

    int k0 = t * 4;
    float r4[4];
#pragma unroll
    for (int j = 0; j < 4; j++) {
        int k = k0 + j;
        float acc = __half2float(row[k]) * inv4s[0];
#pragma unroll
        for (int si = 1; si < 4; si++) {
            int off = 2048 - (2048 >> si);
            int i0, i1; float w;
            interp_idx(k, si, i0, i1, w);
            acc += (__half2float(row[off + i0]) * (1.0f - w) +
                    __half2float(row[off + i1]) * w) * inv4s[si];
        }
        r4[j] = acc * 0.25f;
    }
    *(float4*)(out + (size_t)OUT_ELEMS + ((size_t)bh * S + q) * S + k0) = *(float4*)r4;
}

// ---------- launch ----------
extern "C" void kernel_launch(void* const* d_in, const int* in_sizes, int n_in,
                              void* d_out, int out_size) {
    const float* q = (const float*)d_in[0];
    const float* k = (const float*)d_in[1];
    const float* v = (const float*)d_in[2];
    const float* W = (const float*)d_in[3];
    const float* b = (const float*)d_in[4];
    float* out = (float*)d_out;

    k_qconv       <<<8192, 256>>>(q);
    k_pool_proj   <<<dim3(64, 4, 32), 256>>>(k, v, W, b);
    k_mcoef       <<<4, 256>>>();
    k_pvp2        <<<dim3(60, 32), 256>>>();
    k_scores_fused<<<dim3(15, 8, 32), 256>>>();
    k_rsum        <<<128, 256>>>();
    k_out_mma     <<<dim3(16, 32), 128>>>(out);
    if (out_size >= (int)(OUT_ELEMS + (size_t)BH * S * S))
        k_attn<<<dim3(1024, 32), 256>>>(out);
}